// round 12
// baseline (speedup 1.0000x reference)
#include <cuda_runtime.h>
#include <cuda_bf16.h>
#include <cstdint>

#define NN 8192
#define INSZ 256
#define HID 128

// ---------------- device global scratch (allocation-free) ----------------
__device__ __align__(256) __nv_bfloat16 g_Ahi[NN * HID];
__device__ __align__(256) __nv_bfloat16 g_Bhi[NN * HID];
__device__ unsigned g_packed[NN * 256];      // pos bits: [r][c/32]
__device__ float g_rowS[NN * 128];           // [i][Jc]
__device__ float g_rowP[NN * 128];
__device__ float g_colS[NN * 64];            // [j][Ic]
__device__ float g_colP[NN * 64];

// ---------------- helpers ----------------
__device__ __forceinline__ uint32_t smem_u32(const void* p) {
    uint32_t a;
    asm("{ .reg .u64 t; cvta.to.shared.u64 t, %1; cvt.u32.u64 %0, t; }" : "=r"(a) : "l"(p));
    return a;
}
__device__ __forceinline__ float ex2f(float x) {
    float y; asm("ex2.approx.ftz.f32 %0, %1;" : "=f"(y) : "f"(x)); return y;
}
__device__ __forceinline__ void ldsm4(uint32_t a, uint32_t& r0, uint32_t& r1,
                                      uint32_t& r2, uint32_t& r3) {
    asm volatile("ldmatrix.sync.aligned.m8n8.x4.shared.b16 {%0,%1,%2,%3}, [%4];"
                 : "=r"(r0), "=r"(r1), "=r"(r2), "=r"(r3) : "r"(a));
}
__device__ __forceinline__ void mma16816(float* d, const uint32_t* a, const uint32_t* b) {
    asm volatile("mma.sync.aligned.m16n8k16.row.col.f32.bf16.bf16.f32 "
                 "{%0,%1,%2,%3}, {%4,%5,%6,%7}, {%8,%9}, {%0,%1,%2,%3};"
                 : "+f"(d[0]), "+f"(d[1]), "+f"(d[2]), "+f"(d[3])
                 : "r"(a[0]), "r"(a[1]), "r"(a[2]), "r"(a[3]), "r"(b[0]), "r"(b[1]));
}
__device__ __forceinline__ void cp16(uint32_t dst, const void* src) {
    asm volatile("cp.async.cg.shared.global [%0], [%1], 16;" :: "r"(dst), "l"(src));
}
__device__ __forceinline__ void cp_commit() {
    asm volatile("cp.async.commit_group;" ::: "memory");
}
__device__ __forceinline__ void cp_wait0() {
    asm volatile("cp.async.wait_group 0;" ::: "memory");
}
__device__ __forceinline__ void cp_wait1() {
    asm volatile("cp.async.wait_group 1;" ::: "memory");
}
__device__ __forceinline__ unsigned long long dup2(float a) {
    unsigned long long r; asm("mov.b64 %0, {%1, %1};" : "=l"(r) : "f"(a)); return r;
}
__device__ __forceinline__ void fma2(unsigned long long& d, unsigned long long a,
                                     unsigned long long b) {
    asm("fma.rn.f32x2 %0, %1, %2, %0;" : "+l"(d) : "l"(a), "l"(b));
}
__device__ __forceinline__ float2 unpk(unsigned long long v) {
    float2 r; asm("mov.b64 {%0, %1}, %2;" : "=f"(r.x), "=f"(r.y) : "l"(v)); return r;
}

// ---------------------------------------------------------------------------
// Kernel 1 (fused): blocks [0,256) = projection (R9 form, K-chunk 64,
// double-buffered cp.async); blocks [256,1280) = pos pack, one warp per ROW,
// depth-2 pipelined int4 loads (keeps the LSU full for the CTA's lifetime).
// ---------------------------------------------------------------------------
#define ZS 68
#define HS 66
#define ZBUF_FLOATS (64 * ZS)       // 4352
#define WBUF_FLOATS (64 * 128)      // 8192
#define PREP_SMEM_FLOATS (2 * ZBUF_FLOATS + 2 * WBUF_FLOATS)   // 25088
#define PREP_SMEM_BYTES  (PREP_SMEM_FLOATS * 4)                // 100352

__global__ void __launch_bounds__(256, 2)
prep_kernel(const float* __restrict__ zA, const float* __restrict__ zB,
            const float* __restrict__ W1, const float* __restrict__ b1,
            const float* __restrict__ W2, const float* __restrict__ b2,
            const int* __restrict__ pos) {
    const int tid = threadIdx.x;

    if (blockIdx.x >= 256) {
        // ---- pack path: warp = one row, 8 chunks pipelined depth-2 ----
        int bid = blockIdx.x - 256;              // 0..1023
        int wid = tid >> 5, lane = tid & 31;
        int r = bid * 8 + wid;                   // row 0..8191
        const int4* rowp = (const int4*)(pos + (size_t)r * NN);
        unsigned wbase = (unsigned)r * 256;

        int4 v[2][8];
        #pragma unroll
        for (int t = 0; t < 8; ++t)
            v[0][t] = __ldcs(&rowp[t * 32 + lane]);

        #pragma unroll 1
        for (int c = 0; c < 8; ++c) {
            const int cur = c & 1;
            if (c < 7) {
                const int nxt = cur ^ 1;
                #pragma unroll
                for (int t = 0; t < 8; ++t)
                    v[nxt][t] = __ldcs(&rowp[(c + 1) * 256 + t * 32 + lane]);
            }
            #pragma unroll
            for (int t = 0; t < 8; ++t) {
                int4 q = v[cur][t];
                unsigned nib = (unsigned)(q.x != 0) | ((unsigned)(q.y != 0) << 1)
                             | ((unsigned)(q.z != 0) << 2) | ((unsigned)(q.w != 0) << 3);
                unsigned x = nib << ((lane & 7) * 4);
                x |= __shfl_xor_sync(0xffffffffu, x, 1);
                x |= __shfl_xor_sync(0xffffffffu, x, 2);
                x |= __shfl_xor_sync(0xffffffffu, x, 4);
                if ((lane & 7) == 0)
                    g_packed[wbase + c * 32 + t * 4 + (lane >> 3)] = x;
            }
        }
        return;
    }

    // ---------------- proj path (R9 form) ----------------
    const bool isA = (blockIdx.x < 128);
    const int blk = blockIdx.x & 127;
    const float* z = isA ? zA : zB;
    __nv_bfloat16* hiDst = isA ? g_Ahi : g_Bhi;

    extern __shared__ float sm[];
    float* zb[2] = { sm, sm + ZBUF_FLOATS };
    float* wb[2] = { sm + 2 * ZBUF_FLOATS, sm + 2 * ZBUF_FLOATS + WBUF_FLOATS };
    float* h_s = sm;                     // [128][HS] aliases z buffers
    const uint32_t sb = smem_u32(sm);
    const uint32_t zbo[2] = { sb, sb + ZBUF_FLOATS * 4 };
    const uint32_t wbo[2] = { sb + 2 * ZBUF_FLOATS * 4,
                              sb + (2 * ZBUF_FLOATS + WBUF_FLOATS) * 4 };

    const int tx = tid & 15, ty = tid >> 4;
    const int R0 = ty * 4, C0 = tx * 8;
    const float* zblk = z + (size_t)blk * 64 * INSZ;

    unsigned long long acc[4][4];
    #pragma unroll
    for (int i = 0; i < 4; ++i)
        #pragma unroll
        for (int jp = 0; jp < 4; ++jp) acc[i][jp] = 0ull;

    // stage chunk 0
    {
        #pragma unroll
        for (int it = 0; it < 4; ++it) {
            int e = it * 256 + tid;
            int r = e >> 4, k4 = (e & 15) * 4;
            cp16(zbo[0] + (r * ZS + k4) * 4, &zblk[r * INSZ + k4]);
        }
        #pragma unroll
        for (int it = 0; it < 8; ++it) {
            int e = it * 256 + tid;
            int k = e >> 5, c4 = (e & 31) * 4;
            cp16(wbo[0] + (k * 128 + c4) * 4, &W1[(size_t)k * HID + c4]);
        }
        cp_commit();
    }

    #pragma unroll 1
    for (int kc = 0; kc < 4; ++kc) {
        const int cur = kc & 1;
        if (kc < 3) {
            const int nxt = (kc + 1) & 1;
            #pragma unroll
            for (int it = 0; it < 4; ++it) {
                int e = it * 256 + tid;
                int r = e >> 4, k4 = (e & 15) * 4;
                cp16(zbo[nxt] + (r * ZS + k4) * 4, &zblk[r * INSZ + (kc + 1) * 64 + k4]);
            }
            #pragma unroll
            for (int it = 0; it < 8; ++it) {
                int e = it * 256 + tid;
                int k = e >> 5, c4 = (e & 31) * 4;
                cp16(wbo[nxt] + (k * 128 + c4) * 4,
                     &W1[(size_t)((kc + 1) * 64 + k) * HID + c4]);
            }
            cp_commit();
            cp_wait1();
        } else {
            cp_wait0();
        }
        __syncthreads();

        const float* z_s = zb[cur];
        const float* w_s = wb[cur];
        #pragma unroll 4
        for (int k = 0; k < 64; ++k) {
            ulonglong2 bb0 = *(const ulonglong2*)&w_s[k * 128 + C0];
            ulonglong2 bb1 = *(const ulonglong2*)&w_s[k * 128 + C0 + 4];
            #pragma unroll
            for (int i = 0; i < 4; ++i) {
                unsigned long long ad = dup2(z_s[(R0 + i) * ZS + k]);
                fma2(acc[i][0], ad, bb0.x);
                fma2(acc[i][1], ad, bb0.y);
                fma2(acc[i][2], ad, bb1.x);
                fma2(acc[i][3], ad, bb1.y);
            }
        }
        __syncthreads();
    }

    float b1c[8];
    #pragma unroll
    for (int j = 0; j < 8; ++j) b1c[j] = b1[C0 + j];
    #pragma unroll
    for (int i = 0; i < 4; ++i) {
        #pragma unroll
        for (int jp = 0; jp < 4; ++jp) {
            float2 v = unpk(acc[i][jp]);
            float x0 = v.x + b1c[2 * jp];
            float x1 = v.y + b1c[2 * jp + 1];
            x0 = (x0 > 0.0f) ? x0 : (ex2f(fmaxf(x0, -30.0f) * 1.4426950408889634f) - 1.0f);
            x1 = (x1 > 0.0f) ? x1 : (ex2f(fmaxf(x1, -30.0f) * 1.4426950408889634f) - 1.0f);
            h_s[(C0 + 2 * jp)     * HS + R0 + i] = x0;
            h_s[(C0 + 2 * jp + 1) * HS + R0 + i] = x1;
        }
    }
    __syncthreads();

    #pragma unroll
    for (int i = 0; i < 4; ++i)
        #pragma unroll
        for (int jp = 0; jp < 4; ++jp) acc[i][jp] = 0ull;

    #pragma unroll 4
    for (int k = 0; k < 128; ++k) {
        ulonglong2 bb0 = *(const ulonglong2*)&W2[(size_t)k * HID + C0];
        ulonglong2 bb1 = *(const ulonglong2*)&W2[(size_t)k * HID + C0 + 4];
        #pragma unroll
        for (int i = 0; i < 4; ++i) {
            unsigned long long ad = dup2(h_s[k * HS + R0 + i]);
            fma2(acc[i][0], ad, bb0.x);
            fma2(acc[i][1], ad, bb0.y);
            fma2(acc[i][2], ad, bb1.x);
            fma2(acc[i][3], ad, bb1.y);
        }
    }

    float b2c[8];
    #pragma unroll
    for (int j = 0; j < 8; ++j) b2c[j] = b2[C0 + j];

    float ss[4];
    #pragma unroll
    for (int i = 0; i < 4; ++i) {
        float s = 0.0f;
        #pragma unroll
        for (int jp = 0; jp < 4; ++jp) {
            float2 v = unpk(acc[i][jp]);
            float x0 = v.x + b2c[2 * jp];
            float x1 = v.y + b2c[2 * jp + 1];
            s = fmaf(x0, x0, s); s = fmaf(x1, x1, s);
        }
        ss[i] = s;
    }
    #pragma unroll
    for (int m = 1; m < 16; m <<= 1)
        #pragma unroll
        for (int i = 0; i < 4; ++i)
            ss[i] += __shfl_xor_sync(0xffffffffu, ss[i], m);

    const float scl = isA ? 7.2134752044448170f : 1.0f;   // 5 * log2(e) on A
    union { __nv_bfloat16 b[8]; uint4 u; } hv;
    #pragma unroll
    for (int i = 0; i < 4; ++i) {
        float inv = scl / fmaxf(sqrtf(ss[i]), 1e-12f);
        int gRow = blk * 64 + R0 + i;
        #pragma unroll
        for (int jp = 0; jp < 4; ++jp) {
            float2 v = unpk(acc[i][jp]);
            hv.b[2 * jp]     = __float2bfloat16((v.x + b2c[2 * jp]) * inv);
            hv.b[2 * jp + 1] = __float2bfloat16((v.y + b2c[2 * jp + 1]) * inv);
        }
        *(uint4*)&hiDst[(size_t)gRow * HID + C0] = hv.u;
    }
}

// ---------------------------------------------------------------------------
// Kernel 2: fused sim tile 128(M) x 64(N), single bf16 pass, 3 CTAs/SM.
// ---------------------------------------------------------------------------
#define SM_A0 0
#define SM_B0 32768
#define SM_POSR 49152
#define SM_POSC 50176
#define SM_ROWS 0
#define SM_ROWP 1024
#define SM_COLS 2048
#define SM_COLP 3072
#define SIM_SMEM_BYTES 51200

__global__ void __launch_bounds__(256, 3) sim_kernel() {
    const int J = blockIdx.x, I = blockIdx.y;
    extern __shared__ char smc[];
    const uint32_t sb = smem_u32(smc);
    const int tid = threadIdx.x;
    const int lane = tid & 31, wid = tid >> 5;
    const int wm = wid & 3, wn = wid >> 2;

    // ---- async-load operand tiles (swizzled: chunk c -> c ^ (r&7)) ----
    {
        const uint4* srcA0 = (const uint4*)(g_Ahi + (size_t)I * 128 * HID);
        const uint4* srcB0 = (const uint4*)(g_Bhi + (size_t)J * 64 * HID);
        #pragma unroll
        for (int it = 0; it < 8; ++it) {
            int e = it * 256 + tid;
            int r = e >> 4, c = e & 15;
            uint32_t so = r * 256 + ((c ^ (r & 7)) << 4);
            cp16(sb + SM_A0 + so, srcA0 + e);
            if (it < 4) cp16(sb + SM_B0 + so, srcB0 + e);
        }
    }
    unsigned* posR = (unsigned*)(smc + SM_POSR);   // [128 rows][2 words]
    unsigned* posC = (unsigned*)(smc + SM_POSC);   // [64 cols][4 words]
    posR[tid] = g_packed[(size_t)(I * 128 + (tid >> 1)) * 256 + J * 2 + (tid & 1)];
    posC[tid] = g_packed[(size_t)(J * 64 + (tid >> 2)) * 256 + I * 4 + (tid & 3)];
    cp_commit(); cp_wait0();
    __syncthreads();

    // ---- MMA mainloop (single pass) ----
    float d[2][4][4];
    #pragma unroll
    for (int mt = 0; mt < 2; ++mt)
        #pragma unroll
        for (int nt = 0; nt < 4; ++nt)
            #pragma unroll
            for (int k = 0; k < 4; ++k) d[mt][nt][k] = 0.0f;

    const uint32_t aB0 = sb + SM_A0, bB = sb + SM_B0;

    #pragma unroll
    for (int ks = 0; ks < 8; ++ks) {
        uint32_t bf[4][2];
        #pragma unroll
        for (int np = 0; np < 2; ++np) {
            int l = lane & 7, g = lane >> 3;
            int row = wn * 32 + np * 16 + ((g >> 1) << 3) + l;
            int ch  = ks * 2 + (g & 1);
            ldsm4(bB + row * 256 + ((ch ^ (row & 7)) << 4),
                  bf[2 * np][0], bf[2 * np][1], bf[2 * np + 1][0], bf[2 * np + 1][1]);
        }
        uint32_t af0[2][4];
        #pragma unroll
        for (int mt = 0; mt < 2; ++mt) {
            int row = wm * 32 + mt * 16 + (lane & 15);
            int ch  = ks * 2 + (lane >> 4);
            uint32_t so = row * 256 + ((ch ^ (row & 7)) << 4);
            ldsm4(aB0 + so, af0[mt][0], af0[mt][1], af0[mt][2], af0[mt][3]);
        }
        #pragma unroll
        for (int mt = 0; mt < 2; ++mt)
            #pragma unroll
            for (int nt = 0; nt < 4; ++nt)
                mma16816(d[mt][nt], af0[mt], bf[nt]);
    }
    __syncthreads();

    // ---- epilogue ----
    #pragma unroll
    for (int mt = 0; mt < 2; ++mt)
        #pragma unroll
        for (int nt = 0; nt < 4; ++nt)
            #pragma unroll
            for (int k = 0; k < 4; ++k)
                d[mt][nt][k] = ex2f(d[mt][nt][k]);

    float* rowSsm = (float*)(smc + SM_ROWS);
    float* rowPsm = (float*)(smc + SM_ROWP);
    float* colSsm = (float*)(smc + SM_COLS);
    float* colPsm = (float*)(smc + SM_COLP);

    #pragma unroll
    for (int mt = 0; mt < 2; ++mt) {
        #pragma unroll
        for (int h = 0; h < 2; ++h) {
            int iloc = wm * 32 + mt * 16 + h * 8 + (lane >> 2);
            unsigned w = posR[iloc * 2 + wn];
            float s = 0.0f, p = 0.0f;
            #pragma unroll
            for (int nt = 0; nt < 4; ++nt)
                #pragma unroll
                for (int b = 0; b < 2; ++b) {
                    float e = d[mt][nt][h * 2 + b];
                    s += e;
                    int bit = nt * 8 + (lane & 3) * 2 + b;
                    if ((w >> bit) & 1u) p += e;
                }
            s += __shfl_xor_sync(0xffffffffu, s, 1);
            s += __shfl_xor_sync(0xffffffffu, s, 2);
            p += __shfl_xor_sync(0xffffffffu, p, 1);
            p += __shfl_xor_sync(0xffffffffu, p, 2);
            if ((lane & 3) == 0) {
                rowSsm[wn * 128 + iloc] = s;
                rowPsm[wn * 128 + iloc] = p;
            }
        }
    }

    #pragma unroll
    for (int nt = 0; nt < 4; ++nt) {
        #pragma unroll
        for (int b = 0; b < 2; ++b) {
            int jloc = wn * 32 + nt * 8 + (lane & 3) * 2 + b;
            unsigned w = posC[jloc * 4 + wm];
            float s = 0.0f, p = 0.0f;
            #pragma unroll
            for (int mt = 0; mt < 2; ++mt)
                #pragma unroll
                for (int h = 0; h < 2; ++h) {
                    float e = d[mt][nt][h * 2 + b];
                    s += e;
                    int bit = mt * 16 + h * 8 + (lane >> 2);
                    if ((w >> bit) & 1u) p += e;
                }
            s += __shfl_xor_sync(0xffffffffu, s, 4);
            s += __shfl_xor_sync(0xffffffffu, s, 8);
            s += __shfl_xor_sync(0xffffffffu, s, 16);
            p += __shfl_xor_sync(0xffffffffu, p, 4);
            p += __shfl_xor_sync(0xffffffffu, p, 8);
            p += __shfl_xor_sync(0xffffffffu, p, 16);
            if ((lane >> 2) == 0) {
                colSsm[wm * 64 + jloc] = s;
                colPsm[wm * 64 + jloc] = p;
            }
        }
    }
    __syncthreads();

    if (tid < 128) {
        float rs = rowSsm[tid] + rowSsm[128 + tid];
        float rp = rowPsm[tid] + rowPsm[128 + tid];
        g_rowS[(size_t)(I * 128 + tid) * 128 + J] = rs;
        g_rowP[(size_t)(I * 128 + tid) * 128 + J] = rp;
    } else if (tid < 192) {
        int j = tid - 128;
        float cs = colSsm[j] + colSsm[64 + j] + colSsm[128 + j] + colSsm[192 + j];
        float cp = colPsm[j] + colPsm[64 + j] + colPsm[128 + j] + colPsm[192 + j];
        g_colS[(size_t)(J * 64 + j) * 64 + I] = cs;
        g_colP[(size_t)(J * 64 + j) * 64 + I] = cp;
    }
}

// ---------------------------------------------------------------------------
// Kernel 3: final reduction, 4 threads per row
// ---------------------------------------------------------------------------
__global__ void __launch_bounds__(256) finish_kernel(float* __restrict__ out) {
    int g = blockIdx.x * 256 + threadIdx.x;   // grid 128 x 256 = 32768
    int i = g >> 2, q = g & 3;
    const float4* r4s = (const float4*)&g_rowS[(size_t)i * 128];
    const float4* r4p = (const float4*)&g_rowP[(size_t)i * 128];
    const float4* c4s = (const float4*)&g_colS[(size_t)i * 64];
    const float4* c4p = (const float4*)&g_colP[(size_t)i * 64];
    float rs = 0.0f, rp = 0.0f, cs = 0.0f, cp = 0.0f;
    #pragma unroll
    for (int t = 0; t < 8; ++t) {
        float4 a = r4s[q * 8 + t], b = r4p[q * 8 + t];
        rs += (a.x + a.y) + (a.z + a.w);
        rp += (b.x + b.y) + (b.z + b.w);
    }
    #pragma unroll
    for (int t = 0; t < 4; ++t) {
        float4 a = c4s[q * 4 + t], b = c4p[q * 4 + t];
        cs += (a.x + a.y) + (a.z + a.w);
        cp += (b.x + b.y) + (b.z + b.w);
    }
    #pragma unroll
    for (int m = 1; m < 4; m <<= 1) {
        rs += __shfl_xor_sync(0xffffffffu, rs, m);
        rp += __shfl_xor_sync(0xffffffffu, rp, m);
        cs += __shfl_xor_sync(0xffffffffu, cs, m);
        cp += __shfl_xor_sync(0xffffffffu, cp, m);
    }
    if (q == 0) {
        float mp = rp / (rs + 1e-8f);
        float sc = cp / (cs + 1e-8f);
        float ans = 0.5f * (-logf(mp + 1e-8f)) + 0.5f * (-logf(sc + 1e-8f));
        if (isnan(ans) || isinf(ans)) ans = 0.0f;
        out[i] = ans;
    }
}

extern "C" void kernel_launch(void* const* d_in, const int* in_sizes, int n_in,
                              void* d_out, int out_size) {
    const float* z_mp = (const float*)d_in[0];
    const float* z_sc = (const float*)d_in[1];
    const float* W1   = (const float*)d_in[2];
    const float* b1   = (const float*)d_in[3];
    const float* W2   = (const float*)d_in[4];
    const float* b2   = (const float*)d_in[5];
    const int*   pos  = (const int*)d_in[6];
    float* out = (float*)d_out;

    cudaFuncSetAttribute(prep_kernel, cudaFuncAttributeMaxDynamicSharedMemorySize,
                         PREP_SMEM_BYTES);
    cudaFuncSetAttribute(sim_kernel, cudaFuncAttributeMaxDynamicSharedMemorySize,
                         SIM_SMEM_BYTES);

    prep_kernel<<<1280, 256, PREP_SMEM_BYTES>>>(z_mp, z_sc, W1, b1, W2, b2, pos);
    sim_kernel<<<dim3(128, 64), 256, SIM_SMEM_BYTES>>>();
    finish_kernel<<<128, 256>>>(out);
}

// round 13
// speedup vs baseline: 1.4791x; 1.4791x over previous
#include <cuda_runtime.h>
#include <cuda_bf16.h>
#include <cstdint>

#define NN 8192
#define INSZ 256
#define HID 128

// ---------------- device global scratch (allocation-free) ----------------
__device__ __align__(256) __nv_bfloat16 g_Ahi[NN * HID];
__device__ __align__(256) __nv_bfloat16 g_Bhi[NN * HID];
__device__ __align__(256) __nv_bfloat16 g_W1T[HID * INSZ];   // [n][k] bf16
__device__ __align__(256) __nv_bfloat16 g_W2T[HID * HID];    // [n][k] bf16
__device__ unsigned g_packed[NN * 256];      // pos bits: [r][c/32]
__device__ float g_rowS[NN * 128];           // [i][Jc]
__device__ float g_rowP[NN * 128];
__device__ float g_colS[NN * 64];            // [j][Ic]
__device__ float g_colP[NN * 64];

// ---------------- helpers ----------------
__device__ __forceinline__ uint32_t smem_u32(const void* p) {
    uint32_t a;
    asm("{ .reg .u64 t; cvta.to.shared.u64 t, %1; cvt.u32.u64 %0, t; }" : "=r"(a) : "l"(p));
    return a;
}
__device__ __forceinline__ float ex2f(float x) {
    float y; asm("ex2.approx.ftz.f32 %0, %1;" : "=f"(y) : "f"(x)); return y;
}
__device__ __forceinline__ void ldsm4(uint32_t a, uint32_t& r0, uint32_t& r1,
                                      uint32_t& r2, uint32_t& r3) {
    asm volatile("ldmatrix.sync.aligned.m8n8.x4.shared.b16 {%0,%1,%2,%3}, [%4];"
                 : "=r"(r0), "=r"(r1), "=r"(r2), "=r"(r3) : "r"(a));
}
__device__ __forceinline__ void mma16816(float* d, const uint32_t* a, const uint32_t* b) {
    asm volatile("mma.sync.aligned.m16n8k16.row.col.f32.bf16.bf16.f32 "
                 "{%0,%1,%2,%3}, {%4,%5,%6,%7}, {%8,%9}, {%0,%1,%2,%3};"
                 : "+f"(d[0]), "+f"(d[1]), "+f"(d[2]), "+f"(d[3])
                 : "r"(a[0]), "r"(a[1]), "r"(a[2]), "r"(a[3]), "r"(b[0]), "r"(b[1]));
}
__device__ __forceinline__ void cp16(uint32_t dst, const void* src) {
    asm volatile("cp.async.cg.shared.global [%0], [%1], 16;" :: "r"(dst), "l"(src));
}
__device__ __forceinline__ void cp_commit() {
    asm volatile("cp.async.commit_group;" ::: "memory");
}
__device__ __forceinline__ void cp_wait0() {
    asm volatile("cp.async.wait_group 0;" ::: "memory");
}

union U8 { __nv_bfloat16 b[8]; uint4 u; };
union U2 { __nv_bfloat16 b[2]; unsigned u; };

// ---------------------------------------------------------------------------
// Kernel 0: transpose W1/W2 to bf16 [n][k] (runs once, 3 blocks).
// ---------------------------------------------------------------------------
__global__ void __launch_bounds__(256) wtrans_kernel(const float* __restrict__ W1,
                                                     const float* __restrict__ W2) {
    __shared__ __nv_bfloat16 buf[128 * 136];
    const int tid = threadIdx.x;
    const float* src;
    __nv_bfloat16* dst;
    int kw, koff;
    if (blockIdx.x < 2) { src = W1 + blockIdx.x * 128 * HID; dst = g_W1T; kw = 256; koff = blockIdx.x * 128; }
    else                { src = W2;                          dst = g_W2T; kw = 128; koff = 0; }

    #pragma unroll
    for (int it = 0; it < 16; ++it) {
        int e = it * 256 + tid;              // 4096 float4
        int k = e >> 5, c4 = (e & 31) * 4;
        float4 v = *(const float4*)&src[(size_t)k * HID + c4];
        U2 p0, p1;
        p0.b[0] = __float2bfloat16(v.x); p0.b[1] = __float2bfloat16(v.y);
        p1.b[0] = __float2bfloat16(v.z); p1.b[1] = __float2bfloat16(v.w);
        *(uint2*)&buf[k * 136 + c4] = make_uint2(p0.u, p1.u);
    }
    __syncthreads();
    #pragma unroll
    for (int it = 0; it < 8; ++it) {
        int e = it * 256 + tid;              // 2048 uint4
        int c = e >> 4, kg = (e & 15) * 8;
        U8 t;
        #pragma unroll
        for (int k = 0; k < 8; ++k) t.b[k] = buf[(kg + k) * 136 + c];
        *(uint4*)&dst[(size_t)c * kw + koff + kg] = t.u;
    }
}

// ---------------------------------------------------------------------------
// Kernel 1 (fused): blocks [0,256) = HMMA projection; blocks [256,8448) = pack.
// proj: 64 rows/CTA; phase A = z@W1 (bf16, K=256 in 2 chunks), ELU in regs,
// phase B = h@W2 (K=128); L2-norm epilogue; bf16 output (A scaled 5*log2e).
// ---------------------------------------------------------------------------
#define PJ_A 0           // 16KB [64][128] bf16 swizzled (z chunk, then h)
#define PJ_B 16384       // 32KB [128][128] bf16 swizzled (W1T chunk / W2T)
#define PJ_RED 49152     // 256 floats
#define PREP_SMEM_BYTES (49152 + 1024)

__global__ void __launch_bounds__(256, 2)
prep_kernel(const float* __restrict__ zA, const float* __restrict__ zB,
            const float* __restrict__ b1, const float* __restrict__ b2,
            const int* __restrict__ pos) {
    const int tid = threadIdx.x;

    if (blockIdx.x >= 256) {
        // ---------------- pack path (R9 form) ----------------
        int bid = blockIdx.x - 256;              // 0..8191
        int gw = bid * 8 + (tid >> 5);           // 0..65535
        int lane = tid & 31;
        int r = gw >> 3;
        int chunk = gw & 7;                      // 1024-col chunk
        const int4* base = (const int4*)(pos + (size_t)r * NN + chunk * 1024);
        unsigned wordsBase = (unsigned)r * 256 + chunk * 32;

        int4 v[8];
        #pragma unroll
        for (int t = 0; t < 8; ++t) v[t] = __ldcs(&base[t * 32 + lane]);

        #pragma unroll
        for (int t = 0; t < 8; ++t) {
            unsigned nib = (unsigned)(v[t].x != 0) | ((unsigned)(v[t].y != 0) << 1)
                         | ((unsigned)(v[t].z != 0) << 2) | ((unsigned)(v[t].w != 0) << 3);
            unsigned x = nib << ((lane & 7) * 4);
            x |= __shfl_xor_sync(0xffffffffu, x, 1);
            x |= __shfl_xor_sync(0xffffffffu, x, 2);
            x |= __shfl_xor_sync(0xffffffffu, x, 4);
            if ((lane & 7) == 0)
                g_packed[wordsBase + t * 4 + (lane >> 3)] = x;
        }
        return;
    }

    // ---------------- proj path (HMMA) ----------------
    const bool isA = (blockIdx.x < 128);
    const int blk = blockIdx.x & 127;
    const float* z = isA ? zA : zB;
    __nv_bfloat16* hiDst = isA ? g_Ahi : g_Bhi;

    extern __shared__ char smc[];
    const uint32_t sb = smem_u32(smc);
    float* red = (float*)(smc + PJ_RED);

    const int lane = tid & 31, wid = tid >> 5;
    const int wm = wid & 1, wn = wid >> 1;    // 2(M) x 4(N) warp grid
    const float* zblk = z + (size_t)blk * 64 * INSZ;

    float d[2][4][4];
    #pragma unroll
    for (int mt = 0; mt < 2; ++mt)
        #pragma unroll
        for (int nt = 0; nt < 4; ++nt)
            #pragma unroll
            for (int k = 0; k < 4; ++k) d[mt][nt][k] = 0.0f;

    // ---- phase A: K = 256 in 2 chunks of 128 ----
    #pragma unroll 1
    for (int kc = 0; kc < 2; ++kc) {
        // W1T chunk -> B tile (cp.async, swizzled)
        #pragma unroll
        for (int it = 0; it < 8; ++it) {
            int e = it * 256 + tid;
            int n = e >> 4, g = e & 15;
            cp16(sb + PJ_B + n * 256 + ((g ^ (n & 7)) << 4),
                 (const char*)g_W1T + (size_t)n * 512 + kc * 256 + g * 16);
        }
        cp_commit();
        // z chunk: LDG fp32 -> bf16 -> STS (swizzled)
        #pragma unroll
        for (int it = 0; it < 4; ++it) {
            int e = it * 256 + tid;            // 1024 out-chunks of 16B
            int r = e >> 4, g = e & 15;
            const float* zp = &zblk[r * INSZ + kc * 128 + g * 8];
            float4 f0 = *(const float4*)zp;
            float4 f1 = *(const float4*)(zp + 4);
            U8 hv;
            hv.b[0] = __float2bfloat16(f0.x); hv.b[1] = __float2bfloat16(f0.y);
            hv.b[2] = __float2bfloat16(f0.z); hv.b[3] = __float2bfloat16(f0.w);
            hv.b[4] = __float2bfloat16(f1.x); hv.b[5] = __float2bfloat16(f1.y);
            hv.b[6] = __float2bfloat16(f1.z); hv.b[7] = __float2bfloat16(f1.w);
            *(uint4*)(smc + PJ_A + r * 256 + ((g ^ (r & 7)) << 4)) = hv.u;
        }
        cp_wait0();
        __syncthreads();

        #pragma unroll
        for (int ks = 0; ks < 8; ++ks) {
            uint32_t bf[4][2];
            #pragma unroll
            for (int np = 0; np < 2; ++np) {
                int l = lane & 7, g = lane >> 3;
                int row = wn * 32 + np * 16 + ((g >> 1) << 3) + l;
                int ch  = ks * 2 + (g & 1);
                ldsm4(sb + PJ_B + row * 256 + ((ch ^ (row & 7)) << 4),
                      bf[2 * np][0], bf[2 * np][1], bf[2 * np + 1][0], bf[2 * np + 1][1]);
            }
            uint32_t af[2][4];
            #pragma unroll
            for (int mt = 0; mt < 2; ++mt) {
                int row = wm * 32 + mt * 16 + (lane & 15);
                int ch  = ks * 2 + (lane >> 4);
                ldsm4(sb + PJ_A + row * 256 + ((ch ^ (row & 7)) << 4),
                      af[mt][0], af[mt][1], af[mt][2], af[mt][3]);
            }
            #pragma unroll
            for (int mt = 0; mt < 2; ++mt)
                #pragma unroll
                for (int nt = 0; nt < 4; ++nt)
                    mma16816(d[mt][nt], af[mt], bf[nt]);
        }
        __syncthreads();
    }

    // prefetch W2T into B tile (B free after the sync above)
    #pragma unroll
    for (int it = 0; it < 8; ++it) {
        int e = it * 256 + tid;
        int n = e >> 4, g = e & 15;
        cp16(sb + PJ_B + n * 256 + ((g ^ (n & 7)) << 4),
             (const char*)g_W2T + (size_t)n * 256 + g * 16);
    }
    cp_commit();

    // bias + ELU in regs -> h (bf16) into A tile
    float b1c[8];
    #pragma unroll
    for (int nt = 0; nt < 4; ++nt)
        #pragma unroll
        for (int b = 0; b < 2; ++b)
            b1c[nt * 2 + b] = b1[wn * 32 + nt * 8 + (lane & 3) * 2 + b];

    #pragma unroll
    for (int mt = 0; mt < 2; ++mt) {
        #pragma unroll
        for (int h = 0; h < 2; ++h) {
            int row = wm * 32 + mt * 16 + h * 8 + (lane >> 2);
            #pragma unroll
            for (int nt = 0; nt < 4; ++nt) {
                float x0 = d[mt][nt][h * 2]     + b1c[nt * 2];
                float x1 = d[mt][nt][h * 2 + 1] + b1c[nt * 2 + 1];
                x0 = (x0 > 0.0f) ? x0 : (ex2f(fmaxf(x0, -30.0f) * 1.4426950408889634f) - 1.0f);
                x1 = (x1 > 0.0f) ? x1 : (ex2f(fmaxf(x1, -30.0f) * 1.4426950408889634f) - 1.0f);
                U2 p; p.b[0] = __float2bfloat16(x0); p.b[1] = __float2bfloat16(x1);
                int cb = (wn * 32 + nt * 8 + (lane & 3) * 2) * 2;   // byte offset
                *(uint32_t*)(smc + PJ_A + row * 256 +
                             (((cb >> 4) ^ (row & 7)) << 4) + (cb & 15)) = p.u;
            }
        }
    }
    cp_wait0();
    __syncthreads();

    // ---- phase B: out = h @ W2T, K = 128 ----
    #pragma unroll
    for (int mt = 0; mt < 2; ++mt)
        #pragma unroll
        for (int nt = 0; nt < 4; ++nt)
            #pragma unroll
            for (int k = 0; k < 4; ++k) d[mt][nt][k] = 0.0f;

    #pragma unroll
    for (int ks = 0; ks < 8; ++ks) {
        uint32_t bf[4][2];
        #pragma unroll
        for (int np = 0; np < 2; ++np) {
            int l = lane & 7, g = lane >> 3;
            int row = wn * 32 + np * 16 + ((g >> 1) << 3) + l;
            int ch  = ks * 2 + (g & 1);
            ldsm4(sb + PJ_B + row * 256 + ((ch ^ (row & 7)) << 4),
                  bf[2 * np][0], bf[2 * np][1], bf[2 * np + 1][0], bf[2 * np + 1][1]);
        }
        uint32_t af[2][4];
        #pragma unroll
        for (int mt = 0; mt < 2; ++mt) {
            int row = wm * 32 + mt * 16 + (lane & 15);
            int ch  = ks * 2 + (lane >> 4);
            ldsm4(sb + PJ_A + row * 256 + ((ch ^ (row & 7)) << 4),
                  af[mt][0], af[mt][1], af[mt][2], af[mt][3]);
        }
        #pragma unroll
        for (int mt = 0; mt < 2; ++mt)
            #pragma unroll
            for (int nt = 0; nt < 4; ++nt)
                mma16816(d[mt][nt], af[mt], bf[nt]);
    }
    __syncthreads();

    // ---- epilogue: bias, row sum-of-squares, normalize, write bf16 ----
    float b2c[8];
    #pragma unroll
    for (int nt = 0; nt < 4; ++nt)
        #pragma unroll
        for (int b = 0; b < 2; ++b)
            b2c[nt * 2 + b] = b2[wn * 32 + nt * 8 + (lane & 3) * 2 + b];

    #pragma unroll
    for (int mt = 0; mt < 2; ++mt) {
        #pragma unroll
        for (int h = 0; h < 2; ++h) {
            int row = wm * 32 + mt * 16 + h * 8 + (lane >> 2);
            float s = 0.0f;
            #pragma unroll
            for (int nt = 0; nt < 4; ++nt)
                #pragma unroll
                for (int b = 0; b < 2; ++b) {
                    float x = d[mt][nt][h * 2 + b] + b2c[nt * 2 + b];
                    s = fmaf(x, x, s);
                }
            s += __shfl_xor_sync(0xffffffffu, s, 1);
            s += __shfl_xor_sync(0xffffffffu, s, 2);
            if ((lane & 3) == 0) red[wn * 64 + row] = s;
        }
    }
    __syncthreads();

    const float scl = isA ? 7.2134752044448170f : 1.0f;   // 5 * log2(e) on A
    #pragma unroll
    for (int mt = 0; mt < 2; ++mt) {
        #pragma unroll
        for (int h = 0; h < 2; ++h) {
            int row = wm * 32 + mt * 16 + h * 8 + (lane >> 2);
            float tot = red[row] + red[64 + row] + red[128 + row] + red[192 + row];
            float inv = scl / fmaxf(sqrtf(tot), 1e-12f);
            int grow = blk * 64 + row;
            #pragma unroll
            for (int nt = 0; nt < 4; ++nt) {
                float x0 = (d[mt][nt][h * 2]     + b2c[nt * 2])     * inv;
                float x1 = (d[mt][nt][h * 2 + 1] + b2c[nt * 2 + 1]) * inv;
                U2 p; p.b[0] = __float2bfloat16(x0); p.b[1] = __float2bfloat16(x1);
                *(unsigned*)&hiDst[(size_t)grow * HID + wn * 32 + nt * 8 + (lane & 3) * 2] = p.u;
            }
        }
    }
}

// ---------------------------------------------------------------------------
// Kernel 2: fused sim tile 128(M) x 64(N), single bf16 pass, 3 CTAs/SM.
// ---------------------------------------------------------------------------
#define SM_A0 0
#define SM_B0 32768
#define SM_POSR 49152
#define SM_POSC 50176
#define SM_ROWS 0
#define SM_ROWP 1024
#define SM_COLS 2048
#define SM_COLP 3072
#define SIM_SMEM_BYTES 51200

__global__ void __launch_bounds__(256, 3) sim_kernel() {
    const int J = blockIdx.x, I = blockIdx.y;
    extern __shared__ char smc[];
    const uint32_t sb = smem_u32(smc);
    const int tid = threadIdx.x;
    const int lane = tid & 31, wid = tid >> 5;
    const int wm = wid & 3, wn = wid >> 2;

    {
        const uint4* srcA0 = (const uint4*)(g_Ahi + (size_t)I * 128 * HID);
        const uint4* srcB0 = (const uint4*)(g_Bhi + (size_t)J * 64 * HID);
        #pragma unroll
        for (int it = 0; it < 8; ++it) {
            int e = it * 256 + tid;
            int r = e >> 4, c = e & 15;
            uint32_t so = r * 256 + ((c ^ (r & 7)) << 4);
            cp16(sb + SM_A0 + so, srcA0 + e);
            if (it < 4) cp16(sb + SM_B0 + so, srcB0 + e);
        }
    }
    unsigned* posR = (unsigned*)(smc + SM_POSR);
    unsigned* posC = (unsigned*)(smc + SM_POSC);
    posR[tid] = g_packed[(size_t)(I * 128 + (tid >> 1)) * 256 + J * 2 + (tid & 1)];
    posC[tid] = g_packed[(size_t)(J * 64 + (tid >> 2)) * 256 + I * 4 + (tid & 3)];
    cp_commit(); cp_wait0();
    __syncthreads();

    float d[2][4][4];
    #pragma unroll
    for (int mt = 0; mt < 2; ++mt)
        #pragma unroll
        for (int nt = 0; nt < 4; ++nt)
            #pragma unroll
            for (int k = 0; k < 4; ++k) d[mt][nt][k] = 0.0f;

    const uint32_t aB0 = sb + SM_A0, bB = sb + SM_B0;

    #pragma unroll
    for (int ks = 0; ks < 8; ++ks) {
        uint32_t bf[4][2];
        #pragma unroll
        for (int np = 0; np < 2; ++np) {
            int l = lane & 7, g = lane >> 3;
            int row = wn * 32 + np * 16 + ((g >> 1) << 3) + l;
            int ch  = ks * 2 + (g & 1);
            ldsm4(bB + row * 256 + ((ch ^ (row & 7)) << 4),
                  bf[2 * np][0], bf[2 * np][1], bf[2 * np + 1][0], bf[2 * np + 1][1]);
        }
        uint32_t af0[2][4];
        #pragma unroll
        for (int mt = 0; mt < 2; ++mt) {
            int row = wm * 32 + mt * 16 + (lane & 15);
            int ch  = ks * 2 + (lane >> 4);
            uint32_t so = row * 256 + ((ch ^ (row & 7)) << 4);
            ldsm4(aB0 + so, af0[mt][0], af0[mt][1], af0[mt][2], af0[mt][3]);
        }
        #pragma unroll
        for (int mt = 0; mt < 2; ++mt)
            #pragma unroll
            for (int nt = 0; nt < 4; ++nt)
                mma16816(d[mt][nt], af0[mt], bf[nt]);
    }
    __syncthreads();

    #pragma unroll
    for (int mt = 0; mt < 2; ++mt)
        #pragma unroll
        for (int nt = 0; nt < 4; ++nt)
            #pragma unroll
            for (int k = 0; k < 4; ++k)
                d[mt][nt][k] = ex2f(d[mt][nt][k]);

    float* rowSsm = (float*)(smc + SM_ROWS);
    float* rowPsm = (float*)(smc + SM_ROWP);
    float* colSsm = (float*)(smc + SM_COLS);
    float* colPsm = (float*)(smc + SM_COLP);

    #pragma unroll
    for (int mt = 0; mt < 2; ++mt) {
        #pragma unroll
        for (int h = 0; h < 2; ++h) {
            int iloc = wm * 32 + mt * 16 + h * 8 + (lane >> 2);
            unsigned w = posR[iloc * 2 + wn];
            float s = 0.0f, p = 0.0f;
            #pragma unroll
            for (int nt = 0; nt < 4; ++nt)
                #pragma unroll
                for (int b = 0; b < 2; ++b) {
                    float e = d[mt][nt][h * 2 + b];
                    s += e;
                    int bit = nt * 8 + (lane & 3) * 2 + b;
                    if ((w >> bit) & 1u) p += e;
                }
            s += __shfl_xor_sync(0xffffffffu, s, 1);
            s += __shfl_xor_sync(0xffffffffu, s, 2);
            p += __shfl_xor_sync(0xffffffffu, p, 1);
            p += __shfl_xor_sync(0xffffffffu, p, 2);
            if ((lane & 3) == 0) {
                rowSsm[wn * 128 + iloc] = s;
                rowPsm[wn * 128 + iloc] = p;
            }
        }
    }

    #pragma unroll
    for (int nt = 0; nt < 4; ++nt) {
        #pragma unroll
        for (int b = 0; b < 2; ++b) {
            int jloc = wn * 32 + nt * 8 + (lane & 3) * 2 + b;
            unsigned w = posC[jloc * 4 + wm];
            float s = 0.0f, p = 0.0f;
            #pragma unroll
            for (int mt = 0; mt < 2; ++mt)
                #pragma unroll
                for (int h = 0; h < 2; ++h) {
                    float e = d[mt][nt][h * 2 + b];
                    s += e;
                    int bit = mt * 16 + h * 8 + (lane >> 2);
                    if ((w >> bit) & 1u) p += e;
                }
            s += __shfl_xor_sync(0xffffffffu, s, 4);
            s += __shfl_xor_sync(0xffffffffu, s, 8);
            s += __shfl_xor_sync(0xffffffffu, s, 16);
            p += __shfl_xor_sync(0xffffffffu, p, 4);
            p += __shfl_xor_sync(0xffffffffu, p, 8);
            p += __shfl_xor_sync(0xffffffffu, p, 16);
            if ((lane >> 2) == 0) {
                colSsm[wm * 64 + jloc] = s;
                colPsm[wm * 64 + jloc] = p;
            }
        }
    }
    __syncthreads();

    if (tid < 128) {
        float rs = rowSsm[tid] + rowSsm[128 + tid];
        float rp = rowPsm[tid] + rowPsm[128 + tid];
        g_rowS[(size_t)(I * 128 + tid) * 128 + J] = rs;
        g_rowP[(size_t)(I * 128 + tid) * 128 + J] = rp;
    } else if (tid < 192) {
        int j = tid - 128;
        float cs = colSsm[j] + colSsm[64 + j] + colSsm[128 + j] + colSsm[192 + j];
        float cp = colPsm[j] + colPsm[64 + j] + colPsm[128 + j] + colPsm[192 + j];
        g_colS[(size_t)(J * 64 + j) * 64 + I] = cs;
        g_colP[(size_t)(J * 64 + j) * 64 + I] = cp;
    }
}

// ---------------------------------------------------------------------------
// Kernel 3: final reduction, 4 threads per row
// ---------------------------------------------------------------------------
__global__ void __launch_bounds__(256) finish_kernel(float* __restrict__ out) {
    int g = blockIdx.x * 256 + threadIdx.x;
    int i = g >> 2, q = g & 3;
    const float4* r4s = (const float4*)&g_rowS[(size_t)i * 128];
    const float4* r4p = (const float4*)&g_rowP[(size_t)i * 128];
    const float4* c4s = (const float4*)&g_colS[(size_t)i * 64];
    const float4* c4p = (const float4*)&g_colP[(size_t)i * 64];
    float rs = 0.0f, rp = 0.0f, cs = 0.0f, cp = 0.0f;
    #pragma unroll
    for (int t = 0; t < 8; ++t) {
        float4 a = r4s[q * 8 + t], b = r4p[q * 8 + t];
        rs += (a.x + a.y) + (a.z + a.w);
        rp += (b.x + b.y) + (b.z + b.w);
    }
    #pragma unroll
    for (int t = 0; t < 4; ++t) {
        float4 a = c4s[q * 4 + t], b = c4p[q * 4 + t];
        cs += (a.x + a.y) + (a.z + a.w);
        cp += (b.x + b.y) + (b.z + b.w);
    }
    #pragma unroll
    for (int m = 1; m < 4; m <<= 1) {
        rs += __shfl_xor_sync(0xffffffffu, rs, m);
        rp += __shfl_xor_sync(0xffffffffu, rp, m);
        cs += __shfl_xor_sync(0xffffffffu, cs, m);
        cp += __shfl_xor_sync(0xffffffffu, cp, m);
    }
    if (q == 0) {
        float mp = rp / (rs + 1e-8f);
        float sc = cp / (cs + 1e-8f);
        float ans = 0.5f * (-logf(mp + 1e-8f)) + 0.5f * (-logf(sc + 1e-8f));
        if (isnan(ans) || isinf(ans)) ans = 0.0f;
        out[i] = ans;
    }
}

extern "C" void kernel_launch(void* const* d_in, const int* in_sizes, int n_in,
                              void* d_out, int out_size) {
    const float* z_mp = (const float*)d_in[0];
    const float* z_sc = (const float*)d_in[1];
    const float* W1   = (const float*)d_in[2];
    const float* b1   = (const float*)d_in[3];
    const float* W2   = (const float*)d_in[4];
    const float* b2   = (const float*)d_in[5];
    const int*   pos  = (const int*)d_in[6];
    float* out = (float*)d_out;

    cudaFuncSetAttribute(prep_kernel, cudaFuncAttributeMaxDynamicSharedMemorySize,
                         PREP_SMEM_BYTES);
    cudaFuncSetAttribute(sim_kernel, cudaFuncAttributeMaxDynamicSharedMemorySize,
                         SIM_SMEM_BYTES);

    wtrans_kernel<<<3, 256>>>(W1, W2);
    prep_kernel<<<8448, 256, PREP_SMEM_BYTES>>>(z_mp, z_sc, b1, b2, pos);
    sim_kernel<<<dim3(128, 64), 256, SIM_SMEM_BYTES>>>();
    finish_kernel<<<128, 256>>>(out);
}

// round 14
// speedup vs baseline: 1.6247x; 1.0984x over previous
#include <cuda_runtime.h>
#include <cuda_bf16.h>
#include <cstdint>

#define NN 8192
#define INSZ 256
#define HID 128

// ---------------- device global scratch (allocation-free) ----------------
__device__ __align__(256) __nv_bfloat16 g_Ahi[NN * HID];
__device__ __align__(256) __nv_bfloat16 g_Bhi[NN * HID];
__device__ __align__(256) __nv_bfloat16 g_W1T[HID * INSZ];   // [n][k] bf16
__device__ __align__(256) __nv_bfloat16 g_W2T[HID * HID];    // [n][k] bf16
__device__ unsigned g_packed[NN * 256];      // pos bits: [r][c/32]
__device__ float g_rowS[NN * 64];            // [i][Jc]  Jc in 0..63
__device__ float g_rowP[NN * 64];
__device__ float g_colS[NN * 64];            // [j][Ic]  Ic in 0..63
__device__ float g_colP[NN * 64];

// ---------------- helpers ----------------
__device__ __forceinline__ uint32_t smem_u32(const void* p) {
    uint32_t a;
    asm("{ .reg .u64 t; cvta.to.shared.u64 t, %1; cvt.u32.u64 %0, t; }" : "=r"(a) : "l"(p));
    return a;
}
__device__ __forceinline__ float ex2f(float x) {
    float y; asm("ex2.approx.ftz.f32 %0, %1;" : "=f"(y) : "f"(x)); return y;
}
__device__ __forceinline__ void ldsm4(uint32_t a, uint32_t& r0, uint32_t& r1,
                                      uint32_t& r2, uint32_t& r3) {
    asm volatile("ldmatrix.sync.aligned.m8n8.x4.shared.b16 {%0,%1,%2,%3}, [%4];"
                 : "=r"(r0), "=r"(r1), "=r"(r2), "=r"(r3) : "r"(a));
}
__device__ __forceinline__ void mma16816(float* d, const uint32_t* a, const uint32_t* b) {
    asm volatile("mma.sync.aligned.m16n8k16.row.col.f32.bf16.bf16.f32 "
                 "{%0,%1,%2,%3}, {%4,%5,%6,%7}, {%8,%9}, {%0,%1,%2,%3};"
                 : "+f"(d[0]), "+f"(d[1]), "+f"(d[2]), "+f"(d[3])
                 : "r"(a[0]), "r"(a[1]), "r"(a[2]), "r"(a[3]), "r"(b[0]), "r"(b[1]));
}
__device__ __forceinline__ void cp16(uint32_t dst, const void* src) {
    asm volatile("cp.async.cg.shared.global [%0], [%1], 16;" :: "r"(dst), "l"(src));
}
__device__ __forceinline__ void cp_commit() {
    asm volatile("cp.async.commit_group;" ::: "memory");
}
__device__ __forceinline__ void cp_wait0() {
    asm volatile("cp.async.wait_group 0;" ::: "memory");
}

union U8 { __nv_bfloat16 b[8]; uint4 u; };
union U2 { __nv_bfloat16 b[2]; unsigned u; };

// ---------------------------------------------------------------------------
// Kernel 0: transpose W1/W2 to bf16 [n][k] (runs once, 3 blocks).
// ---------------------------------------------------------------------------
__global__ void __launch_bounds__(256) wtrans_kernel(const float* __restrict__ W1,
                                                     const float* __restrict__ W2) {
    __shared__ __nv_bfloat16 buf[128 * 136];
    const int tid = threadIdx.x;
    const float* src;
    __nv_bfloat16* dst;
    int kw, koff;
    if (blockIdx.x < 2) { src = W1 + blockIdx.x * 128 * HID; dst = g_W1T; kw = 256; koff = blockIdx.x * 128; }
    else                { src = W2;                          dst = g_W2T; kw = 128; koff = 0; }

    #pragma unroll
    for (int it = 0; it < 16; ++it) {
        int e = it * 256 + tid;
        int k = e >> 5, c4 = (e & 31) * 4;
        float4 v = *(const float4*)&src[(size_t)k * HID + c4];
        U2 p0, p1;
        p0.b[0] = __float2bfloat16(v.x); p0.b[1] = __float2bfloat16(v.y);
        p1.b[0] = __float2bfloat16(v.z); p1.b[1] = __float2bfloat16(v.w);
        *(uint2*)&buf[k * 136 + c4] = make_uint2(p0.u, p1.u);
    }
    __syncthreads();
    #pragma unroll
    for (int it = 0; it < 8; ++it) {
        int e = it * 256 + tid;
        int c = e >> 4, kg = (e & 15) * 8;
        U8 t;
        #pragma unroll
        for (int k = 0; k < 8; ++k) t.b[k] = buf[(kg + k) * 136 + c];
        *(uint4*)&dst[(size_t)c * kw + koff + kg] = t.u;
    }
}

// ---------------------------------------------------------------------------
// Kernel 1 (fused): blocks [0,256) = HMMA projection; blocks [256,8448) = pack.
// ---------------------------------------------------------------------------
#define PJ_A 0
#define PJ_B 16384
#define PJ_RED 49152
#define PREP_SMEM_BYTES (49152 + 1024)

__global__ void __launch_bounds__(256, 2)
prep_kernel(const float* __restrict__ zA, const float* __restrict__ zB,
            const float* __restrict__ b1, const float* __restrict__ b2,
            const int* __restrict__ pos) {
    const int tid = threadIdx.x;

    if (blockIdx.x >= 256) {
        int bid = blockIdx.x - 256;
        int gw = bid * 8 + (tid >> 5);
        int lane = tid & 31;
        int r = gw >> 3;
        int chunk = gw & 7;
        const int4* base = (const int4*)(pos + (size_t)r * NN + chunk * 1024);
        unsigned wordsBase = (unsigned)r * 256 + chunk * 32;

        int4 v[8];
        #pragma unroll
        for (int t = 0; t < 8; ++t) v[t] = __ldcs(&base[t * 32 + lane]);

        #pragma unroll
        for (int t = 0; t < 8; ++t) {
            unsigned nib = (unsigned)(v[t].x != 0) | ((unsigned)(v[t].y != 0) << 1)
                         | ((unsigned)(v[t].z != 0) << 2) | ((unsigned)(v[t].w != 0) << 3);
            unsigned x = nib << ((lane & 7) * 4);
            x |= __shfl_xor_sync(0xffffffffu, x, 1);
            x |= __shfl_xor_sync(0xffffffffu, x, 2);
            x |= __shfl_xor_sync(0xffffffffu, x, 4);
            if ((lane & 7) == 0)
                g_packed[wordsBase + t * 4 + (lane >> 3)] = x;
        }
        return;
    }

    // ---------------- proj path (HMMA) ----------------
    const bool isA = (blockIdx.x < 128);
    const int blk = blockIdx.x & 127;
    const float* z = isA ? zA : zB;
    __nv_bfloat16* hiDst = isA ? g_Ahi : g_Bhi;

    extern __shared__ char smc[];
    const uint32_t sb = smem_u32(smc);
    float* red = (float*)(smc + PJ_RED);

    const int lane = tid & 31, wid = tid >> 5;
    const int wm = wid & 1, wn = wid >> 1;
    const float* zblk = z + (size_t)blk * 64 * INSZ;

    float d[2][4][4];
    #pragma unroll
    for (int mt = 0; mt < 2; ++mt)
        #pragma unroll
        for (int nt = 0; nt < 4; ++nt)
            #pragma unroll
            for (int k = 0; k < 4; ++k) d[mt][nt][k] = 0.0f;

    #pragma unroll 1
    for (int kc = 0; kc < 2; ++kc) {
        #pragma unroll
        for (int it = 0; it < 8; ++it) {
            int e = it * 256 + tid;
            int n = e >> 4, g = e & 15;
            cp16(sb + PJ_B + n * 256 + ((g ^ (n & 7)) << 4),
                 (const char*)g_W1T + (size_t)n * 512 + kc * 256 + g * 16);
        }
        cp_commit();
        #pragma unroll
        for (int it = 0; it < 4; ++it) {
            int e = it * 256 + tid;
            int r = e >> 4, g = e & 15;
            const float* zp = &zblk[r * INSZ + kc * 128 + g * 8];
            float4 f0 = *(const float4*)zp;
            float4 f1 = *(const float4*)(zp + 4);
            U8 hv;
            hv.b[0] = __float2bfloat16(f0.x); hv.b[1] = __float2bfloat16(f0.y);
            hv.b[2] = __float2bfloat16(f0.z); hv.b[3] = __float2bfloat16(f0.w);
            hv.b[4] = __float2bfloat16(f1.x); hv.b[5] = __float2bfloat16(f1.y);
            hv.b[6] = __float2bfloat16(f1.z); hv.b[7] = __float2bfloat16(f1.w);
            *(uint4*)(smc + PJ_A + r * 256 + ((g ^ (r & 7)) << 4)) = hv.u;
        }
        cp_wait0();
        __syncthreads();

        #pragma unroll
        for (int ks = 0; ks < 8; ++ks) {
            uint32_t bf[4][2];
            #pragma unroll
            for (int np = 0; np < 2; ++np) {
                int l = lane & 7, g = lane >> 3;
                int row = wn * 32 + np * 16 + ((g >> 1) << 3) + l;
                int ch  = ks * 2 + (g & 1);
                ldsm4(sb + PJ_B + row * 256 + ((ch ^ (row & 7)) << 4),
                      bf[2 * np][0], bf[2 * np][1], bf[2 * np + 1][0], bf[2 * np + 1][1]);
            }
            uint32_t af[2][4];
            #pragma unroll
            for (int mt = 0; mt < 2; ++mt) {
                int row = wm * 32 + mt * 16 + (lane & 15);
                int ch  = ks * 2 + (lane >> 4);
                ldsm4(sb + PJ_A + row * 256 + ((ch ^ (row & 7)) << 4),
                      af[mt][0], af[mt][1], af[mt][2], af[mt][3]);
            }
            #pragma unroll
            for (int mt = 0; mt < 2; ++mt)
                #pragma unroll
                for (int nt = 0; nt < 4; ++nt)
                    mma16816(d[mt][nt], af[mt], bf[nt]);
        }
        __syncthreads();
    }

    #pragma unroll
    for (int it = 0; it < 8; ++it) {
        int e = it * 256 + tid;
        int n = e >> 4, g = e & 15;
        cp16(sb + PJ_B + n * 256 + ((g ^ (n & 7)) << 4),
             (const char*)g_W2T + (size_t)n * 256 + g * 16);
    }
    cp_commit();

    float b1c[8];
    #pragma unroll
    for (int nt = 0; nt < 4; ++nt)
        #pragma unroll
        for (int b = 0; b < 2; ++b)
            b1c[nt * 2 + b] = b1[wn * 32 + nt * 8 + (lane & 3) * 2 + b];

    #pragma unroll
    for (int mt = 0; mt < 2; ++mt) {
        #pragma unroll
        for (int h = 0; h < 2; ++h) {
            int row = wm * 32 + mt * 16 + h * 8 + (lane >> 2);
            #pragma unroll
            for (int nt = 0; nt < 4; ++nt) {
                float x0 = d[mt][nt][h * 2]     + b1c[nt * 2];
                float x1 = d[mt][nt][h * 2 + 1] + b1c[nt * 2 + 1];
                x0 = (x0 > 0.0f) ? x0 : (ex2f(fmaxf(x0, -30.0f) * 1.4426950408889634f) - 1.0f);
                x1 = (x1 > 0.0f) ? x1 : (ex2f(fmaxf(x1, -30.0f) * 1.4426950408889634f) - 1.0f);
                U2 p; p.b[0] = __float2bfloat16(x0); p.b[1] = __float2bfloat16(x1);
                int cb = (wn * 32 + nt * 8 + (lane & 3) * 2) * 2;
                *(uint32_t*)(smc + PJ_A + row * 256 +
                             (((cb >> 4) ^ (row & 7)) << 4) + (cb & 15)) = p.u;
            }
        }
    }
    cp_wait0();
    __syncthreads();

    #pragma unroll
    for (int mt = 0; mt < 2; ++mt)
        #pragma unroll
        for (int nt = 0; nt < 4; ++nt)
            #pragma unroll
            for (int k = 0; k < 4; ++k) d[mt][nt][k] = 0.0f;

    #pragma unroll
    for (int ks = 0; ks < 8; ++ks) {
        uint32_t bf[4][2];
        #pragma unroll
        for (int np = 0; np < 2; ++np) {
            int l = lane & 7, g = lane >> 3;
            int row = wn * 32 + np * 16 + ((g >> 1) << 3) + l;
            int ch  = ks * 2 + (g & 1);
            ldsm4(sb + PJ_B + row * 256 + ((ch ^ (row & 7)) << 4),
                  bf[2 * np][0], bf[2 * np][1], bf[2 * np + 1][0], bf[2 * np + 1][1]);
        }
        uint32_t af[2][4];
        #pragma unroll
        for (int mt = 0; mt < 2; ++mt) {
            int row = wm * 32 + mt * 16 + (lane & 15);
            int ch  = ks * 2 + (lane >> 4);
            ldsm4(sb + PJ_A + row * 256 + ((ch ^ (row & 7)) << 4),
                  af[mt][0], af[mt][1], af[mt][2], af[mt][3]);
        }
        #pragma unroll
        for (int mt = 0; mt < 2; ++mt)
            #pragma unroll
            for (int nt = 0; nt < 4; ++nt)
                mma16816(d[mt][nt], af[mt], bf[nt]);
    }
    __syncthreads();

    float b2c[8];
    #pragma unroll
    for (int nt = 0; nt < 4; ++nt)
        #pragma unroll
        for (int b = 0; b < 2; ++b)
            b2c[nt * 2 + b] = b2[wn * 32 + nt * 8 + (lane & 3) * 2 + b];

    #pragma unroll
    for (int mt = 0; mt < 2; ++mt) {
        #pragma unroll
        for (int h = 0; h < 2; ++h) {
            int row = wm * 32 + mt * 16 + h * 8 + (lane >> 2);
            float s = 0.0f;
            #pragma unroll
            for (int nt = 0; nt < 4; ++nt)
                #pragma unroll
                for (int b = 0; b < 2; ++b) {
                    float x = d[mt][nt][h * 2 + b] + b2c[nt * 2 + b];
                    s = fmaf(x, x, s);
                }
            s += __shfl_xor_sync(0xffffffffu, s, 1);
            s += __shfl_xor_sync(0xffffffffu, s, 2);
            if ((lane & 3) == 0) red[wn * 64 + row] = s;
        }
    }
    __syncthreads();

    const float scl = isA ? 7.2134752044448170f : 1.0f;
    #pragma unroll
    for (int mt = 0; mt < 2; ++mt) {
        #pragma unroll
        for (int h = 0; h < 2; ++h) {
            int row = wm * 32 + mt * 16 + h * 8 + (lane >> 2);
            float tot = red[row] + red[64 + row] + red[128 + row] + red[192 + row];
            float inv = scl / fmaxf(sqrtf(tot), 1e-12f);
            int grow = blk * 64 + row;
            #pragma unroll
            for (int nt = 0; nt < 4; ++nt) {
                float x0 = (d[mt][nt][h * 2]     + b2c[nt * 2])     * inv;
                float x1 = (d[mt][nt][h * 2 + 1] + b2c[nt * 2 + 1]) * inv;
                U2 p; p.b[0] = __float2bfloat16(x0); p.b[1] = __float2bfloat16(x1);
                *(unsigned*)&hiDst[(size_t)grow * HID + wn * 32 + nt * 8 + (lane & 3) * 2] = p.u;
            }
        }
    }
}

// ---------------------------------------------------------------------------
// Kernel 2: fused sim tile 128(M) x 128(N), single bf16 pass, 2 CTAs/SM.
// grid = (J=64, I=64), 256 threads = 8 warps (4 M-bands x 2 N-bands of 64).
// ---------------------------------------------------------------------------
#define SM_A0 0
#define SM_B0 32768
#define SM_POSR 65536                 // 512 words
#define SM_POSC (65536 + 2048)        // 512 words
#define SM_ROWS 0                     // [2][128] floats
#define SM_ROWP 1024
#define SM_COLS 2048                  // [4][128] floats
#define SM_COLP 4096
#define SIM_SMEM_BYTES (65536 + 4096)

__global__ void __launch_bounds__(256, 2) sim_kernel() {
    const int J = blockIdx.x, I = blockIdx.y;
    extern __shared__ char smc[];
    const uint32_t sb = smem_u32(smc);
    const int tid = threadIdx.x;
    const int lane = tid & 31, wid = tid >> 5;
    const int wm = wid & 3, wn = wid >> 2;   // rows wm*32..+31, cols wn*64..+63

    // ---- async-load operand tiles (swizzled: chunk c -> c ^ (r&7)) ----
    {
        const uint4* srcA0 = (const uint4*)(g_Ahi + (size_t)I * 128 * HID);
        const uint4* srcB0 = (const uint4*)(g_Bhi + (size_t)J * 128 * HID);
        #pragma unroll
        for (int it = 0; it < 8; ++it) {
            int e = it * 256 + tid;
            int r = e >> 4, c = e & 15;
            uint32_t so = r * 256 + ((c ^ (r & 7)) << 4);
            cp16(sb + SM_A0 + so, srcA0 + e);
            cp16(sb + SM_B0 + so, srcB0 + e);
        }
    }
    unsigned* posR = (unsigned*)(smc + SM_POSR);   // [128 rows][4 words]
    unsigned* posC = (unsigned*)(smc + SM_POSC);   // [128 cols][4 words]
    #pragma unroll
    for (int e = tid; e < 512; e += 256) {
        posR[e] = g_packed[(size_t)(I * 128 + (e >> 2)) * 256 + J * 4 + (e & 3)];
        posC[e] = g_packed[(size_t)(J * 128 + (e >> 2)) * 256 + I * 4 + (e & 3)];
    }
    cp_commit(); cp_wait0();
    __syncthreads();

    // ---- MMA mainloop (single pass) ----
    float d[2][8][4];
    #pragma unroll
    for (int mt = 0; mt < 2; ++mt)
        #pragma unroll
        for (int nt = 0; nt < 8; ++nt)
            #pragma unroll
            for (int k = 0; k < 4; ++k) d[mt][nt][k] = 0.0f;

    const uint32_t aB0 = sb + SM_A0, bB = sb + SM_B0;

    #pragma unroll
    for (int ks = 0; ks < 8; ++ks) {
        uint32_t bf[8][2];
        #pragma unroll
        for (int np = 0; np < 4; ++np) {
            int l = lane & 7, g = lane >> 3;
            int row = wn * 64 + np * 16 + ((g >> 1) << 3) + l;
            int ch  = ks * 2 + (g & 1);
            ldsm4(bB + row * 256 + ((ch ^ (row & 7)) << 4),
                  bf[2 * np][0], bf[2 * np][1], bf[2 * np + 1][0], bf[2 * np + 1][1]);
        }
        uint32_t af0[2][4];
        #pragma unroll
        for (int mt = 0; mt < 2; ++mt) {
            int row = wm * 32 + mt * 16 + (lane & 15);
            int ch  = ks * 2 + (lane >> 4);
            uint32_t so = row * 256 + ((ch ^ (row & 7)) << 4);
            ldsm4(aB0 + so, af0[mt][0], af0[mt][1], af0[mt][2], af0[mt][3]);
        }
        #pragma unroll
        for (int mt = 0; mt < 2; ++mt)
            #pragma unroll
            for (int nt = 0; nt < 8; ++nt)
                mma16816(d[mt][nt], af0[mt], bf[nt]);
    }
    __syncthreads();   // operand smem reused for reduction buffers

    // ---- epilogue: exp2 + masked reductions ----
    #pragma unroll
    for (int mt = 0; mt < 2; ++mt)
        #pragma unroll
        for (int nt = 0; nt < 8; ++nt)
            #pragma unroll
            for (int k = 0; k < 4; ++k)
                d[mt][nt][k] = ex2f(d[mt][nt][k]);

    float* rowSsm = (float*)(smc + SM_ROWS);
    float* rowPsm = (float*)(smc + SM_ROWP);
    float* colSsm = (float*)(smc + SM_COLS);
    float* colPsm = (float*)(smc + SM_COLP);

    // row sums: thread covers rows (mt,h); 16 cols (8 nt x 2 b) in its 64-band
    #pragma unroll
    for (int mt = 0; mt < 2; ++mt) {
        #pragma unroll
        for (int h = 0; h < 2; ++h) {
            int iloc = wm * 32 + mt * 16 + h * 8 + (lane >> 2);
            unsigned w0 = posR[iloc * 4 + wn * 2];
            unsigned w1 = posR[iloc * 4 + wn * 2 + 1];
            float s = 0.0f, p = 0.0f;
            #pragma unroll
            for (int nt = 0; nt < 8; ++nt) {
                unsigned w = (nt < 4) ? w0 : w1;
                #pragma unroll
                for (int b = 0; b < 2; ++b) {
                    float e = d[mt][nt][h * 2 + b];
                    s += e;
                    int bit = (nt & 3) * 8 + (lane & 3) * 2 + b;
                    if ((w >> bit) & 1u) p += e;
                }
            }
            s += __shfl_xor_sync(0xffffffffu, s, 1);
            s += __shfl_xor_sync(0xffffffffu, s, 2);
            p += __shfl_xor_sync(0xffffffffu, p, 1);
            p += __shfl_xor_sync(0xffffffffu, p, 2);
            if ((lane & 3) == 0) {
                rowSsm[wn * 128 + iloc] = s;
                rowPsm[wn * 128 + iloc] = p;
            }
        }
    }

    // col sums: thread covers 16 cols (nt x b); 4 rows (mt x h) each
    #pragma unroll
    for (int nt = 0; nt < 8; ++nt) {
        #pragma unroll
        for (int b = 0; b < 2; ++b) {
            int jloc = wn * 64 + nt * 8 + (lane & 3) * 2 + b;
            unsigned w = posC[jloc * 4 + wm];
            float s = 0.0f, p = 0.0f;
            #pragma unroll
            for (int mt = 0; mt < 2; ++mt)
                #pragma unroll
                for (int h = 0; h < 2; ++h) {
                    float e = d[mt][nt][h * 2 + b];
                    s += e;
                    int bit = mt * 16 + h * 8 + (lane >> 2);
                    if ((w >> bit) & 1u) p += e;
                }
            s += __shfl_xor_sync(0xffffffffu, s, 4);
            s += __shfl_xor_sync(0xffffffffu, s, 8);
            s += __shfl_xor_sync(0xffffffffu, s, 16);
            p += __shfl_xor_sync(0xffffffffu, p, 4);
            p += __shfl_xor_sync(0xffffffffu, p, 8);
            p += __shfl_xor_sync(0xffffffffu, p, 16);
            if ((lane >> 2) == 0) {
                colSsm[wm * 128 + jloc] = s;
                colPsm[wm * 128 + jloc] = p;
            }
        }
    }
    __syncthreads();

    // partial writes in [i][chunk] layout
    if (tid < 128) {
        float rs = rowSsm[tid] + rowSsm[128 + tid];
        float rp = rowPsm[tid] + rowPsm[128 + tid];
        g_rowS[(size_t)(I * 128 + tid) * 64 + J] = rs;
        g_rowP[(size_t)(I * 128 + tid) * 64 + J] = rp;
    } else {
        int j = tid - 128;
        float cs = colSsm[j] + colSsm[128 + j] + colSsm[256 + j] + colSsm[384 + j];
        float cp = colPsm[j] + colPsm[128 + j] + colPsm[256 + j] + colPsm[384 + j];
        g_colS[(size_t)(J * 128 + j) * 64 + I] = cs;
        g_colP[(size_t)(J * 128 + j) * 64 + I] = cp;
    }
}

// ---------------------------------------------------------------------------
// Kernel 3: final reduction, 4 threads per row
// ---------------------------------------------------------------------------
__global__ void __launch_bounds__(256) finish_kernel(float* __restrict__ out) {
    int g = blockIdx.x * 256 + threadIdx.x;   // grid 128 x 256 = 32768
    int i = g >> 2, q = g & 3;
    const float4* r4s = (const float4*)&g_rowS[(size_t)i * 64];
    const float4* r4p = (const float4*)&g_rowP[(size_t)i * 64];
    const float4* c4s = (const float4*)&g_colS[(size_t)i * 64];
    const float4* c4p = (const float4*)&g_colP[(size_t)i * 64];
    float rs = 0.0f, rp = 0.0f, cs = 0.0f, cp = 0.0f;
    #pragma unroll
    for (int t = 0; t < 4; ++t) {
        float4 a = r4s[q * 4 + t], b = r4p[q * 4 + t];
        rs += (a.x + a.y) + (a.z + a.w);
        rp += (b.x + b.y) + (b.z + b.w);
        float4 c = c4s[q * 4 + t], e = c4p[q * 4 + t];
        cs += (c.x + c.y) + (c.z + c.w);
        cp += (e.x + e.y) + (e.z + e.w);
    }
    #pragma unroll
    for (int m = 1; m < 4; m <<= 1) {
        rs += __shfl_xor_sync(0xffffffffu, rs, m);
        rp += __shfl_xor_sync(0xffffffffu, rp, m);
        cs += __shfl_xor_sync(0xffffffffu, cs, m);
        cp += __shfl_xor_sync(0xffffffffu, cp, m);
    }
    if (q == 0) {
        float mp = rp / (rs + 1e-8f);
        float sc = cp / (cs + 1e-8f);
        float ans = 0.5f * (-logf(mp + 1e-8f)) + 0.5f * (-logf(sc + 1e-8f));
        if (isnan(ans) || isinf(ans)) ans = 0.0f;
        out[i] = ans;
    }
}

extern "C" void kernel_launch(void* const* d_in, const int* in_sizes, int n_in,
                              void* d_out, int out_size) {
    const float* z_mp = (const float*)d_in[0];
    const float* z_sc = (const float*)d_in[1];
    const float* W1   = (const float*)d_in[2];
    const float* b1   = (const float*)d_in[3];
    const float* W2   = (const float*)d_in[4];
    const float* b2   = (const float*)d_in[5];
    const int*   pos  = (const int*)d_in[6];
    float* out = (float*)d_out;

    cudaFuncSetAttribute(prep_kernel, cudaFuncAttributeMaxDynamicSharedMemorySize,
                         PREP_SMEM_BYTES);
    cudaFuncSetAttribute(sim_kernel, cudaFuncAttributeMaxDynamicSharedMemorySize,
                         SIM_SMEM_BYTES);

    wtrans_kernel<<<3, 256>>>(W1, W2);
    prep_kernel<<<8448, 256, PREP_SMEM_BYTES>>>(z_mp, z_sc, b1, b2, pos);
    sim_kernel<<<dim3(64, 64), 256, SIM_SMEM_BYTES>>>();
    finish_kernel<<<128, 256>>>(out);
}